// round 3
// baseline (speedup 1.0000x reference)
#include <cuda_runtime.h>
#include <cuda_bf16.h>
#include <math.h>

#define N_NODES 100000
#define N_EDGES 3200000
#define N_GRAPHS 64
#define F 16

// ---------------- scratch (static device memory; no allocation) ----------------
__device__ int   d_deg[N_NODES];      // out-degree over row (source)
__device__ int   d_cnt[N_NODES];      // in-count over col (target), for mean
__device__ float d_dis[N_NODES];      // deg_inv_sqrt
__device__ float d_cinv[N_NODES];     // 1/max(cnt,1)
__device__ float d_aggr[N_NODES * F]; // scatter accumulator (6.4MB, L2-resident)
__device__ float d_h[N_NODES * F];    // layer-1 output features
__device__ float d_g[N_GRAPHS * F];   // pooled sums
__device__ int   d_gcnt[N_GRAPHS];    // nodes per graph

// ---------------- kernels ----------------

// zero all accumulators in one pass
__global__ void k_init() {
    int i = blockIdx.x * blockDim.x + threadIdx.x;
    if (i < N_NODES * F) d_aggr[i] = 0.0f;
    if (i < N_NODES) { d_deg[i] = 0; d_cnt[i] = 0; }
    if (i < N_GRAPHS * F) d_g[i] = 0.0f;
    if (i < N_GRAPHS) d_gcnt[i] = 0;
}

// degree/count histograms over int32 edge index
__global__ void k_prep(const int* __restrict__ ei) {
    int e = blockIdx.x * blockDim.x + threadIdx.x;
    if (e >= N_EDGES) return;
    int r = ei[e];
    int c = ei[N_EDGES + e];
    atomicAdd(&d_deg[r], 1);
    atomicAdd(&d_cnt[c], 1);
}

__global__ void k_finalize_deg() {
    int n = blockIdx.x * blockDim.x + threadIdx.x;
    if (n >= N_NODES) return;
    int dg = d_deg[n];
    d_dis[n]  = (dg > 0) ? rsqrtf((float)dg) : 0.0f;
    int cn = d_cnt[n];
    d_cinv[n] = 1.0f / (float)(cn > 0 ? cn : 1);
}

// layer-1 edge kernel: msg = concat(x[row](3), ea(2)) @ Wn1 * norm -> scatter to col
__global__ void k_edge1(const int* __restrict__ ei,
                        const float* __restrict__ x,
                        const float* __restrict__ ea,
                        const float* __restrict__ Wn1) {
    __shared__ float w[5 * F];
    if (threadIdx.x < 5 * F) w[threadIdx.x] = Wn1[threadIdx.x];
    __syncthreads();
    int e = blockIdx.x * blockDim.x + threadIdx.x;
    if (e >= N_EDGES) return;
    int r = ei[e];
    int c = ei[N_EDGES + e];
    float norm = d_dis[r] * d_dis[c];
    float i0 = __ldg(&x[r * 3 + 0]);
    float i1 = __ldg(&x[r * 3 + 1]);
    float i2 = __ldg(&x[r * 3 + 2]);
    float2 eav = ((const float2*)ea)[e];
    float* dst = &d_aggr[c * F];
#pragma unroll
    for (int k = 0; k < F; k++) {
        float m = (i0 * w[k] + i1 * w[F + k]) + (i2 * w[2 * F + k] +
                  (eav.x * w[3 * F + k] + eav.y * w[4 * F + k]));
        atomicAdd(dst + k, m * norm);
    }
}

// layer-1 node kernel: h = relu(x@Wc1 + bc1 + aggr * cinv); re-zero aggr for layer 2
__global__ void k_node1(const float* __restrict__ x,
                        const float* __restrict__ Wc1,
                        const float* __restrict__ bc1) {
    __shared__ float w[3 * F];
    __shared__ float b[F];
    if (threadIdx.x < 3 * F) w[threadIdx.x] = Wc1[threadIdx.x];
    if (threadIdx.x < F) b[threadIdx.x] = bc1[threadIdx.x];
    __syncthreads();
    int n = blockIdx.x * blockDim.x + threadIdx.x;
    if (n >= N_NODES) return;
    float x0 = x[n * 3 + 0], x1 = x[n * 3 + 1], x2 = x[n * 3 + 2];
    float ci = d_cinv[n];
#pragma unroll
    for (int k = 0; k < F; k++) {
        float cent = b[k] + x0 * w[k] + x1 * w[F + k] + x2 * w[2 * F + k];
        float v = cent + d_aggr[n * F + k] * ci;
        d_h[n * F + k] = fmaxf(v, 0.0f);
        d_aggr[n * F + k] = 0.0f;
    }
}

// layer-2 edge kernel: msg = concat(h[row](16), ea(2)) @ Wn2 * norm -> scatter to col
__global__ void k_edge2(const int* __restrict__ ei,
                        const float* __restrict__ ea,
                        const float* __restrict__ Wn2) {
    __shared__ float w[18 * F];
    for (int i = threadIdx.x; i < 18 * F; i += blockDim.x) w[i] = Wn2[i];
    __syncthreads();
    int e = blockIdx.x * blockDim.x + threadIdx.x;
    if (e >= N_EDGES) return;
    int r = ei[e];
    int c = ei[N_EDGES + e];
    float norm = d_dis[r] * d_dis[c];
    const float4* hv = (const float4*)&d_h[r * F];
    float4 h0 = hv[0], h1 = hv[1], h2 = hv[2], h3 = hv[3];
    float in[18];
    in[0] = h0.x; in[1] = h0.y; in[2] = h0.z; in[3] = h0.w;
    in[4] = h1.x; in[5] = h1.y; in[6] = h1.z; in[7] = h1.w;
    in[8] = h2.x; in[9] = h2.y; in[10] = h2.z; in[11] = h2.w;
    in[12] = h3.x; in[13] = h3.y; in[14] = h3.z; in[15] = h3.w;
    float2 eav = ((const float2*)ea)[e];
    in[16] = eav.x; in[17] = eav.y;
    float m[F];
#pragma unroll
    for (int k = 0; k < F; k++) m[k] = 0.0f;
#pragma unroll
    for (int i = 0; i < 18; i++) {
#pragma unroll
        for (int k = 0; k < F; k++) m[k] += in[i] * w[i * F + k];
    }
    float* dst = &d_aggr[c * F];
#pragma unroll
    for (int k = 0; k < F; k++) atomicAdd(dst + k, m[k] * norm);
}

// layer-2 node kernel: h2 = relu(h@Wc2 + bc2 + aggr*cinv); fused graph-pool scatter
__global__ void k_node2(const float* __restrict__ Wc2,
                        const float* __restrict__ bc2,
                        const int* __restrict__ batch) {
    __shared__ float w[F * F];
    __shared__ float b[F];
    for (int i = threadIdx.x; i < F * F; i += blockDim.x) w[i] = Wc2[i];
    if (threadIdx.x < F) b[threadIdx.x] = bc2[threadIdx.x];
    __syncthreads();
    int n = blockIdx.x * blockDim.x + threadIdx.x;
    if (n >= N_NODES) return;
    float hv[F];
    const float4* hp = (const float4*)&d_h[n * F];
#pragma unroll
    for (int q = 0; q < 4; q++) {
        float4 t = hp[q];
        hv[q * 4 + 0] = t.x; hv[q * 4 + 1] = t.y; hv[q * 4 + 2] = t.z; hv[q * 4 + 3] = t.w;
    }
    float ci = d_cinv[n];
    int g = batch[n];
    float* dst = &d_g[g * F];
#pragma unroll
    for (int k = 0; k < F; k++) {
        float cent = b[k];
#pragma unroll
        for (int j = 0; j < F; j++) cent += hv[j] * w[j * F + k];
        float v = fmaxf(cent + d_aggr[n * F + k] * ci, 0.0f);
        atomicAdd(dst + k, v);
    }
    atomicAdd(&d_gcnt[g], 1);
}

// final head: per-graph mean, 2-layer MLP -> out[G,2]
__global__ void k_head(const float* __restrict__ Wl1, const float* __restrict__ bl1,
                       const float* __restrict__ Wl2, const float* __restrict__ bl2,
                       float* __restrict__ out) {
    int g = threadIdx.x;
    if (g >= N_GRAPHS) return;
    int c = d_gcnt[g];
    float inv = 1.0f / (float)(c > 0 ? c : 1);
    float gm[F];
#pragma unroll
    for (int k = 0; k < F; k++) gm[k] = d_g[g * F + k] * inv;
    float t[F];
#pragma unroll
    for (int j = 0; j < F; j++) {
        float a = bl1[j];
#pragma unroll
        for (int k = 0; k < F; k++) a += gm[k] * Wl1[k * F + j];
        t[j] = fmaxf(a, 0.0f);
    }
#pragma unroll
    for (int o = 0; o < 2; o++) {
        float a = bl2[o];
#pragma unroll
        for (int j = 0; j < F; j++) a += t[j] * Wl2[j * 2 + o];
        out[g * 2 + o] = a;
    }
}

// ---------------- launch ----------------
extern "C" void kernel_launch(void* const* d_in, const int* in_sizes, int n_in,
                              void* d_out, int out_size) {
    const float* x     = (const float*)d_in[0];
    const int*   ei    = (const int*)d_in[1];    // int32 (JAX x64 disabled canonicalizes int64->int32)
    const float* ea    = (const float*)d_in[2];
    const int*   batch = (const int*)d_in[3];
    const float* Wc1 = (const float*)d_in[4];
    const float* bc1 = (const float*)d_in[5];
    const float* Wn1 = (const float*)d_in[6];
    const float* Wc2 = (const float*)d_in[7];
    const float* bc2 = (const float*)d_in[8];
    const float* Wn2 = (const float*)d_in[9];
    const float* Wl1 = (const float*)d_in[10];
    const float* bl1 = (const float*)d_in[11];
    const float* Wl2 = (const float*)d_in[12];
    const float* bl2 = (const float*)d_in[13];
    float* out = (float*)d_out;

    const int T = 256;
    int zb = (N_NODES * F + T - 1) / T;
    int eb = (N_EDGES + T - 1) / T;
    int nb = (N_NODES + T - 1) / T;

    k_init<<<zb, T>>>();
    k_prep<<<eb, T>>>(ei);
    k_finalize_deg<<<nb, T>>>();
    k_edge1<<<eb, T>>>(ei, x, ea, Wn1);
    k_node1<<<nb, T>>>(x, Wc1, bc1);
    k_edge2<<<eb, T>>>(ei, ea, Wn2);
    k_node2<<<nb, T>>>(Wc2, bc2, batch);
    k_head<<<1, 64>>>(Wl1, bl1, Wl2, bl2, out);
}

// round 4
// speedup vs baseline: 2.1235x; 2.1235x over previous
#include <cuda_runtime.h>
#include <cuda_bf16.h>
#include <math.h>

#define N_NODES 100000
#define N_EDGES 3200000
#define N_GRAPHS 64
#define F 16

// ---------------- scratch (static device memory; no allocation) ----------------
__device__ int    d_deg[N_NODES];       // out-degree over row (source)
__device__ int    d_cnt[N_NODES];       // in-count over col (target)
__device__ int    d_off[N_NODES];       // CSR offsets (exclusive prefix of cnt)
__device__ int    d_cursor[N_NODES];    // scatter cursors
__device__ int2   d_csr[N_EDGES];       // (row, edge_id) grouped by col
__device__ float  d_dis[N_NODES];       // deg_inv_sqrt
__device__ float  d_cinv[N_NODES];      // 1/max(cnt,1)
__device__ float2 d_zea[N_NODES];       // per-node Σ norm*edge_attr (layer-independent)
__device__ float  d_h[N_NODES * F];     // layer-1 output
__device__ float  d_h2[N_NODES * F];    // layer-2 output
__device__ int    d_gstart[N_GRAPHS + 1];
__device__ float  d_gmean[N_GRAPHS * F];

// ---------------- kernels ----------------

__global__ void k_init() {
    int i = blockIdx.x * blockDim.x + threadIdx.x;
    if (i < N_NODES) { d_deg[i] = 0; d_cnt[i] = 0; }
}

// histograms over int32 edge index
__global__ void k_hist(const int* __restrict__ ei) {
    int e = blockIdx.x * blockDim.x + threadIdx.x;
    if (e >= N_EDGES) return;
    atomicAdd(&d_deg[ei[e]], 1);
    atomicAdd(&d_cnt[ei[N_EDGES + e]], 1);
}

// single-block exclusive prefix scan of d_cnt -> d_off (and cursor copy)
__global__ void k_scan() {
    __shared__ int sm[1024];
    int t = threadIdx.x;
    const int CH = (N_NODES + 1023) / 1024;  // 98
    int base = t * CH;
    int s = 0;
    for (int i = 0; i < CH; i++) {
        int idx = base + i;
        if (idx < N_NODES) s += d_cnt[idx];
    }
    sm[t] = s;
    __syncthreads();
    for (int off = 1; off < 1024; off <<= 1) {
        int v = (t >= off) ? sm[t - off] : 0;
        __syncthreads();
        sm[t] += v;
        __syncthreads();
    }
    int run = (t == 0) ? 0 : sm[t - 1];
    for (int i = 0; i < CH; i++) {
        int idx = base + i;
        if (idx < N_NODES) {
            d_off[idx] = run;
            d_cursor[idx] = run;
            run += d_cnt[idx];
        }
    }
}

__global__ void k_finalize() {
    int n = blockIdx.x * blockDim.x + threadIdx.x;
    if (n >= N_NODES) return;
    int dg = d_deg[n];
    d_dis[n] = (dg > 0) ? rsqrtf((float)dg) : 0.0f;
    int cn = d_cnt[n];
    d_cinv[n] = 1.0f / (float)(cn > 0 ? cn : 1);
}

// scatter edges into CSR grouped by target (col)
__global__ void k_scatter(const int* __restrict__ ei) {
    int e = blockIdx.x * blockDim.x + threadIdx.x;
    if (e >= N_EDGES) return;
    int r = ei[e];
    int c = ei[N_EDGES + e];
    int pos = atomicAdd(&d_cursor[c], 1);
    d_csr[pos] = make_int2(r, e);
}

// layer-1 pull (warp per node) + fused node update:
// z = [Σ norm*x[r] (3), Σ norm*ea (2)];  h = relu(x@Wc1+bc1 + (z@Wn1)*cinv)
__global__ void k_pull1(const float* __restrict__ x,
                        const float* __restrict__ ea,
                        const float* __restrict__ Wn1,
                        const float* __restrict__ Wc1,
                        const float* __restrict__ bc1) {
    int n = (blockIdx.x * blockDim.x + threadIdx.x) >> 5;
    if (n >= N_NODES) return;
    int lane = threadIdx.x & 31;
    int start = d_off[n];
    int end = start + d_cnt[n];
    float disc = d_dis[n];
    float a0 = 0.f, a1 = 0.f, a2 = 0.f, a3 = 0.f, a4 = 0.f;
    for (int i = start + lane; i < end; i += 32) {
        int2 re = d_csr[i];
        float nr = __ldg(&d_dis[re.x]) * disc;
        a0 += nr * __ldg(&x[re.x * 3 + 0]);
        a1 += nr * __ldg(&x[re.x * 3 + 1]);
        a2 += nr * __ldg(&x[re.x * 3 + 2]);
        float2 eav = __ldg(&((const float2*)ea)[re.y]);
        a3 += nr * eav.x;
        a4 += nr * eav.y;
    }
#pragma unroll
    for (int o = 16; o; o >>= 1) {
        a0 += __shfl_xor_sync(0xffffffffu, a0, o);
        a1 += __shfl_xor_sync(0xffffffffu, a1, o);
        a2 += __shfl_xor_sync(0xffffffffu, a2, o);
        a3 += __shfl_xor_sync(0xffffffffu, a3, o);
        a4 += __shfl_xor_sync(0xffffffffu, a4, o);
    }
    if (lane == 0) d_zea[n] = make_float2(a3, a4);
    if (lane < F) {
        int j = lane;
        float ci = d_cinv[n];
        float aggr = (a0 * __ldg(&Wn1[0 * F + j]) + a1 * __ldg(&Wn1[1 * F + j]) +
                      a2 * __ldg(&Wn1[2 * F + j]) + a3 * __ldg(&Wn1[3 * F + j]) +
                      a4 * __ldg(&Wn1[4 * F + j])) * ci;
        float x0 = __ldg(&x[n * 3 + 0]), x1 = __ldg(&x[n * 3 + 1]), x2 = __ldg(&x[n * 3 + 2]);
        float cent = __ldg(&bc1[j]) + x0 * __ldg(&Wc1[0 * F + j]) +
                     x1 * __ldg(&Wc1[1 * F + j]) + x2 * __ldg(&Wc1[2 * F + j]);
        d_h[n * F + j] = fmaxf(cent + aggr, 0.0f);
    }
}

// layer-2 pull (warp per node) + fused node update:
// zh = Σ norm*h[r] (16);  h2 = relu(h@Wc2+bc2 + ([zh,zea]@Wn2)*cinv)
__global__ void k_pull2(const float* __restrict__ Wn2,
                        const float* __restrict__ Wc2,
                        const float* __restrict__ bc2) {
    int n = (blockIdx.x * blockDim.x + threadIdx.x) >> 5;
    if (n >= N_NODES) return;
    int lane = threadIdx.x & 31;
    int start = d_off[n];
    int end = start + d_cnt[n];
    float disc = d_dis[n];
    float acc[F];
#pragma unroll
    for (int k = 0; k < F; k++) acc[k] = 0.0f;
    for (int i = start + lane; i < end; i += 32) {
        int2 re = d_csr[i];
        float nr = __ldg(&d_dis[re.x]) * disc;
        const float4* hp = (const float4*)&d_h[re.x * F];
        float4 v0 = __ldg(&hp[0]), v1 = __ldg(&hp[1]), v2 = __ldg(&hp[2]), v3 = __ldg(&hp[3]);
        acc[0]  += nr * v0.x; acc[1]  += nr * v0.y; acc[2]  += nr * v0.z; acc[3]  += nr * v0.w;
        acc[4]  += nr * v1.x; acc[5]  += nr * v1.y; acc[6]  += nr * v1.z; acc[7]  += nr * v1.w;
        acc[8]  += nr * v2.x; acc[9]  += nr * v2.y; acc[10] += nr * v2.z; acc[11] += nr * v2.w;
        acc[12] += nr * v3.x; acc[13] += nr * v3.y; acc[14] += nr * v3.z; acc[15] += nr * v3.w;
    }
#pragma unroll
    for (int o = 16; o; o >>= 1) {
#pragma unroll
        for (int k = 0; k < F; k++) acc[k] += __shfl_xor_sync(0xffffffffu, acc[k], o);
    }
    if (lane < F) {
        int j = lane;
        float ci = d_cinv[n];
        float2 zea = d_zea[n];
        float aggr = zea.x * __ldg(&Wn2[16 * F + j]) + zea.y * __ldg(&Wn2[17 * F + j]);
#pragma unroll
        for (int k = 0; k < F; k++) aggr += acc[k] * __ldg(&Wn2[k * F + j]);
        aggr *= ci;
        float cent = __ldg(&bc2[j]);
        const float* hn = &d_h[n * F];
#pragma unroll
        for (int k = 0; k < F; k++) cent += hn[k] * __ldg(&Wc2[k * F + j]);
        d_h2[n * F + j] = fmaxf(cent + aggr, 0.0f);
    }
}

// graph segment boundaries from sorted batch
__global__ void k_gbounds(const int* __restrict__ batch) {
    int n = blockIdx.x * blockDim.x + threadIdx.x;
    if (n >= N_NODES) return;
    int b = batch[n];
    if (n == 0) {
        for (int g = 0; g <= b; g++) d_gstart[g] = 0;
    } else {
        int p = batch[n - 1];
        for (int g = p + 1; g <= b; g++) d_gstart[g] = n;
    }
    if (n == N_NODES - 1) {
        for (int g = b + 1; g <= N_GRAPHS; g++) d_gstart[g] = N_NODES;
    }
}

// per-graph mean pooling: one block per graph, coalesced, no atomics
__global__ void k_pool() {
    int g = blockIdx.x;
    int s0 = d_gstart[g], s1 = d_gstart[g + 1];
    int cnt = s1 - s0;
    int t = threadIdx.x;            // 256 threads: t = f + 16*s
    int f = t & 15, s = t >> 4;
    float acc = 0.0f;
    for (int n = s0 + s; n < s1; n += 16) acc += d_h2[n * F + f];
    __shared__ float sm[256];
    sm[t] = acc;
    __syncthreads();
    for (int o = 128; o >= 16; o >>= 1) {
        if (t < o) sm[t] += sm[t + o];
        __syncthreads();
    }
    if (t < F) d_gmean[g * F + t] = sm[t] / (float)(cnt > 0 ? cnt : 1);
}

// head MLP
__global__ void k_head(const float* __restrict__ Wl1, const float* __restrict__ bl1,
                       const float* __restrict__ Wl2, const float* __restrict__ bl2,
                       float* __restrict__ out) {
    int g = threadIdx.x;
    if (g >= N_GRAPHS) return;
    float gm[F];
#pragma unroll
    for (int k = 0; k < F; k++) gm[k] = d_gmean[g * F + k];
    float t[F];
#pragma unroll
    for (int j = 0; j < F; j++) {
        float a = bl1[j];
#pragma unroll
        for (int k = 0; k < F; k++) a += gm[k] * Wl1[k * F + j];
        t[j] = fmaxf(a, 0.0f);
    }
#pragma unroll
    for (int o = 0; o < 2; o++) {
        float a = bl2[o];
#pragma unroll
        for (int j = 0; j < F; j++) a += t[j] * Wl2[j * 2 + o];
        out[g * 2 + o] = a;
    }
}

// ---------------- launch ----------------
extern "C" void kernel_launch(void* const* d_in, const int* in_sizes, int n_in,
                              void* d_out, int out_size) {
    const float* x     = (const float*)d_in[0];
    const int*   ei    = (const int*)d_in[1];
    const float* ea    = (const float*)d_in[2];
    const int*   batch = (const int*)d_in[3];
    const float* Wc1 = (const float*)d_in[4];
    const float* bc1 = (const float*)d_in[5];
    const float* Wn1 = (const float*)d_in[6];
    const float* Wc2 = (const float*)d_in[7];
    const float* bc2 = (const float*)d_in[8];
    const float* Wn2 = (const float*)d_in[9];
    const float* Wl1 = (const float*)d_in[10];
    const float* bl1 = (const float*)d_in[11];
    const float* Wl2 = (const float*)d_in[12];
    const float* bl2 = (const float*)d_in[13];
    float* out = (float*)d_out;

    const int T = 256;
    int eb = (N_EDGES + T - 1) / T;
    int nb = (N_NODES + T - 1) / T;
    int wb = (N_NODES * 32 + T - 1) / T;   // warp-per-node grids

    k_init<<<nb, T>>>();
    k_hist<<<eb, T>>>(ei);
    k_scan<<<1, 1024>>>();
    k_finalize<<<nb, T>>>();
    k_scatter<<<eb, T>>>(ei);
    k_pull1<<<wb, T>>>(x, ea, Wn1, Wc1, bc1);
    k_pull2<<<wb, T>>>(Wn2, Wc2, bc2);
    k_gbounds<<<nb, T>>>(batch);
    k_pool<<<N_GRAPHS, 256>>>();
    k_head<<<1, 64>>>(Wl1, bl1, Wl2, bl2, out);
}

// round 5
// speedup vs baseline: 3.5459x; 1.6698x over previous
#include <cuda_runtime.h>
#include <cuda_bf16.h>
#include <math.h>

#define N_NODES 100000
#define N_EDGES 3200000
#define N_GRAPHS 64
#define F 16
#define NB ((N_NODES + 255) / 256)   // 391 blocks of 256

// ---------------- scratch (static device memory; no allocation) ----------------
__device__ int    d_deg[N_NODES];        // out-degree over row (source)
__device__ int    d_cnt[N_NODES];        // in-count over col (target)
__device__ int    d_off[N_NODES];        // CSR offsets
__device__ int    d_cursor[N_NODES];     // scatter cursors
__device__ int    d_bsum[NB];            // per-block cnt sums
__device__ int    d_bbase[NB];           // scanned block bases
__device__ float4 d_csr[N_EDGES];        // {row_as_float, nr, nr*ea.x, nr*ea.y} grouped by col
__device__ float  d_dis[N_NODES];        // deg_inv_sqrt
__device__ float  d_cinv[N_NODES];       // 1/max(cnt,1)
__device__ float4 d_x4[N_NODES];         // padded node features
__device__ float2 d_zea[N_NODES];        // per-node Σ nr*ea (layer-independent)
__device__ float  d_h[N_NODES * F];      // layer-1 output
__device__ float  d_gsum[N_GRAPHS * F];  // pooled sums
__device__ int    d_gcnt[N_GRAPHS];      // nodes per graph

// ---------------- kernels ----------------

__global__ void k_init() {
    int i = blockIdx.x * blockDim.x + threadIdx.x;
    if (i < N_NODES) { d_deg[i] = 0; d_cnt[i] = 0; }
    if (i < N_GRAPHS * F) d_gsum[i] = 0.0f;
    if (i < N_GRAPHS) d_gcnt[i] = 0;
}

// histograms over int32 edge index
__global__ void k_hist(const int* __restrict__ ei) {
    int e = blockIdx.x * blockDim.x + threadIdx.x;
    if (e >= N_EDGES) return;
    atomicAdd(&d_deg[ei[e]], 1);
    atomicAdd(&d_cnt[ei[N_EDGES + e]], 1);
}

// phase 1: per-block sums of d_cnt
__global__ void k_bsum() {
    __shared__ int sm[256];
    int t = threadIdx.x;
    int n = blockIdx.x * 256 + t;
    sm[t] = (n < N_NODES) ? d_cnt[n] : 0;
    __syncthreads();
    for (int o = 128; o; o >>= 1) {
        if (t < o) sm[t] += sm[t + o];
        __syncthreads();
    }
    if (t == 0) d_bsum[blockIdx.x] = sm[0];
}

// phase 2: exclusive scan of block sums (single block, 512 threads)
__global__ void k_bscan() {
    __shared__ int sm[512];
    int t = threadIdx.x;
    sm[t] = (t < NB) ? d_bsum[t] : 0;
    __syncthreads();
    for (int off = 1; off < 512; off <<= 1) {
        int v = (t >= off) ? sm[t - off] : 0;
        __syncthreads();
        sm[t] += v;
        __syncthreads();
    }
    if (t < NB) d_bbase[t] = (t == 0) ? 0 : sm[t - 1];
}

// phase 3: per-block offsets + finalize (dis, cinv, padded x)
__global__ void k_off(const float* __restrict__ x) {
    __shared__ int sm[256];
    int t = threadIdx.x;
    int n = blockIdx.x * 256 + t;
    int c = (n < N_NODES) ? d_cnt[n] : 0;
    sm[t] = c;
    __syncthreads();
    for (int off = 1; off < 256; off <<= 1) {
        int v = (t >= off) ? sm[t - off] : 0;
        __syncthreads();
        sm[t] += v;
        __syncthreads();
    }
    if (n < N_NODES) {
        int o = d_bbase[blockIdx.x] + sm[t] - c;   // exclusive
        d_off[n] = o;
        d_cursor[n] = o;
        int dg = d_deg[n];
        d_dis[n] = (dg > 0) ? rsqrtf((float)dg) : 0.0f;
        d_cinv[n] = 1.0f / (float)(c > 0 ? c : 1);
        d_x4[n] = make_float4(x[n * 3 + 0], x[n * 3 + 1], x[n * 3 + 2], 0.0f);
    }
}

// scatter edges into fat CSR entries grouped by target (col)
__global__ void k_scatter(const int* __restrict__ ei, const float* __restrict__ ea) {
    int e = blockIdx.x * blockDim.x + threadIdx.x;
    if (e >= N_EDGES) return;
    int r = ei[e];
    int c = ei[N_EDGES + e];
    float nr = __ldg(&d_dis[r]) * __ldg(&d_dis[c]);
    float2 eav = __ldg(&((const float2*)ea)[e]);
    int pos = atomicAdd(&d_cursor[c], 1);
    d_csr[pos] = make_float4(__int_as_float(r), nr, nr * eav.x, nr * eav.y);
}

// layer-1 pull (warp per node) + fused node update:
// z = [Σ nr*x[r] (3), Σ nr*ea (2)];  h = relu(x@Wc1+bc1 + (z@Wn1)*cinv)
__global__ void k_pull1(const float* __restrict__ Wn1,
                        const float* __restrict__ Wc1,
                        const float* __restrict__ bc1) {
    int n = (blockIdx.x * blockDim.x + threadIdx.x) >> 5;
    if (n >= N_NODES) return;
    int lane = threadIdx.x & 31;
    int start = d_off[n];
    int end = start + d_cnt[n];
    float a0 = 0.f, a1 = 0.f, a2 = 0.f, a3 = 0.f, a4 = 0.f;
    for (int i = start + lane; i < end; i += 32) {
        float4 en = d_csr[i];
        int r = __float_as_int(en.x);
        float nr = en.y;
        float4 xv = __ldg(&d_x4[r]);
        a0 += nr * xv.x;
        a1 += nr * xv.y;
        a2 += nr * xv.z;
        a3 += en.z;
        a4 += en.w;
    }
#pragma unroll
    for (int o = 16; o; o >>= 1) {
        a0 += __shfl_xor_sync(0xffffffffu, a0, o);
        a1 += __shfl_xor_sync(0xffffffffu, a1, o);
        a2 += __shfl_xor_sync(0xffffffffu, a2, o);
        a3 += __shfl_xor_sync(0xffffffffu, a3, o);
        a4 += __shfl_xor_sync(0xffffffffu, a4, o);
    }
    if (lane == 0) d_zea[n] = make_float2(a3, a4);
    if (lane < F) {
        int j = lane;
        float ci = d_cinv[n];
        float aggr = (a0 * __ldg(&Wn1[0 * F + j]) + a1 * __ldg(&Wn1[1 * F + j]) +
                      a2 * __ldg(&Wn1[2 * F + j]) + a3 * __ldg(&Wn1[3 * F + j]) +
                      a4 * __ldg(&Wn1[4 * F + j])) * ci;
        float4 xv = __ldg(&d_x4[n]);
        float cent = __ldg(&bc1[j]) + xv.x * __ldg(&Wc1[0 * F + j]) +
                     xv.y * __ldg(&Wc1[1 * F + j]) + xv.z * __ldg(&Wc1[2 * F + j]);
        d_h[n * F + j] = fmaxf(cent + aggr, 0.0f);
    }
}

// layer-2 pull (warp per node) + fused node update + fused graph pooling:
// zh = Σ nr*h[r];  v = relu(h@Wc2+bc2 + ([zh,zea]@Wn2)*cinv);  atomic pool
__global__ void k_pull2(const float* __restrict__ Wn2,
                        const float* __restrict__ Wc2,
                        const float* __restrict__ bc2,
                        const int* __restrict__ batch) {
    int n = (blockIdx.x * blockDim.x + threadIdx.x) >> 5;
    if (n >= N_NODES) return;
    int lane = threadIdx.x & 31;
    int start = d_off[n];
    int end = start + d_cnt[n];
    float acc[F];
#pragma unroll
    for (int k = 0; k < F; k++) acc[k] = 0.0f;
    for (int i = start + lane; i < end; i += 32) {
        float4 en = d_csr[i];
        int r = __float_as_int(en.x);
        float nr = en.y;
        const float4* hp = (const float4*)&d_h[r * F];
        float4 v0 = __ldg(&hp[0]), v1 = __ldg(&hp[1]), v2 = __ldg(&hp[2]), v3 = __ldg(&hp[3]);
        acc[0]  += nr * v0.x; acc[1]  += nr * v0.y; acc[2]  += nr * v0.z; acc[3]  += nr * v0.w;
        acc[4]  += nr * v1.x; acc[5]  += nr * v1.y; acc[6]  += nr * v1.z; acc[7]  += nr * v1.w;
        acc[8]  += nr * v2.x; acc[9]  += nr * v2.y; acc[10] += nr * v2.z; acc[11] += nr * v2.w;
        acc[12] += nr * v3.x; acc[13] += nr * v3.y; acc[14] += nr * v3.z; acc[15] += nr * v3.w;
    }
#pragma unroll
    for (int o = 16; o; o >>= 1) {
#pragma unroll
        for (int k = 0; k < F; k++) acc[k] += __shfl_xor_sync(0xffffffffu, acc[k], o);
    }
    int g = __ldg(&batch[n]);
    if (lane == 16) atomicAdd(&d_gcnt[g], 1);
    if (lane < F) {
        int j = lane;
        float ci = d_cinv[n];
        float2 zea = d_zea[n];
        float aggr = zea.x * __ldg(&Wn2[16 * F + j]) + zea.y * __ldg(&Wn2[17 * F + j]);
#pragma unroll
        for (int k = 0; k < F; k++) aggr += acc[k] * __ldg(&Wn2[k * F + j]);
        aggr *= ci;
        float cent = __ldg(&bc2[j]);
        const float* hn = &d_h[n * F];
#pragma unroll
        for (int k = 0; k < F; k++) cent += hn[k] * __ldg(&Wc2[k * F + j]);
        float v = fmaxf(cent + aggr, 0.0f);
        atomicAdd(&d_gsum[g * F + j], v);
    }
}

// head MLP (mean + 2-layer MLP)
__global__ void k_head(const float* __restrict__ Wl1, const float* __restrict__ bl1,
                       const float* __restrict__ Wl2, const float* __restrict__ bl2,
                       float* __restrict__ out) {
    int g = threadIdx.x;
    if (g >= N_GRAPHS) return;
    int c = d_gcnt[g];
    float inv = 1.0f / (float)(c > 0 ? c : 1);
    float gm[F];
#pragma unroll
    for (int k = 0; k < F; k++) gm[k] = d_gsum[g * F + k] * inv;
    float t[F];
#pragma unroll
    for (int j = 0; j < F; j++) {
        float a = bl1[j];
#pragma unroll
        for (int k = 0; k < F; k++) a += gm[k] * Wl1[k * F + j];
        t[j] = fmaxf(a, 0.0f);
    }
#pragma unroll
    for (int o = 0; o < 2; o++) {
        float a = bl2[o];
#pragma unroll
        for (int j = 0; j < F; j++) a += t[j] * Wl2[j * 2 + o];
        out[g * 2 + o] = a;
    }
}

// ---------------- launch ----------------
extern "C" void kernel_launch(void* const* d_in, const int* in_sizes, int n_in,
                              void* d_out, int out_size) {
    const float* x     = (const float*)d_in[0];
    const int*   ei    = (const int*)d_in[1];
    const float* ea    = (const float*)d_in[2];
    const int*   batch = (const int*)d_in[3];
    const float* Wc1 = (const float*)d_in[4];
    const float* bc1 = (const float*)d_in[5];
    const float* Wn1 = (const float*)d_in[6];
    const float* Wc2 = (const float*)d_in[7];
    const float* bc2 = (const float*)d_in[8];
    const float* Wn2 = (const float*)d_in[9];
    const float* Wl1 = (const float*)d_in[10];
    const float* bl1 = (const float*)d_in[11];
    const float* Wl2 = (const float*)d_in[12];
    const float* bl2 = (const float*)d_in[13];
    float* out = (float*)d_out;

    const int T = 256;
    int eb = (N_EDGES + T - 1) / T;
    int wb = (N_NODES * 32 + T - 1) / T;   // warp-per-node grids

    k_init<<<NB, T>>>();
    k_hist<<<eb, T>>>(ei);
    k_bsum<<<NB, T>>>();
    k_bscan<<<1, 512>>>();
    k_off<<<NB, T>>>(x);
    k_scatter<<<eb, T>>>(ei, ea);
    k_pull1<<<wb, T>>>(Wn1, Wc1, bc1);
    k_pull2<<<wb, T>>>(Wn2, Wc2, bc2, batch);
    k_head<<<1, 64>>>(Wl1, bl1, Wl2, bl2, out);
}